// round 2
// baseline (speedup 1.0000x reference)
#include <cuda_runtime.h>

#define M_TOK   100352      // 32 * 56 * 56
#define DIM     256
#define QKV_N   768
#define HEADS   8
#define HD      32
#define WS      7
#define NT      49          // tokens per window
#define SCALE   0.17677669529663687f  // 32^-0.5

// Scratch (device globals: allocation-free per harness rules)
__device__ float g_qkv[(size_t)M_TOK * QKV_N];   // 308 MB
__device__ float g_attn[(size_t)M_TOK * DIM];    // 103 MB

// ---------------------------------------------------------------------------
// Classic 128x128x16 SGEMM, 256 threads, 8x8 per-thread micro-tile.
// All dims here are exact multiples of tiles (M=100352=784*128, N in {768,256},
// K=256), so no predication anywhere.
// ---------------------------------------------------------------------------
__global__ __launch_bounds__(256) void sgemm_kernel(
    const float* __restrict__ A, const float* __restrict__ B,
    float* __restrict__ C, const float* __restrict__ bias,
    int N, int K)
{
    __shared__ float As[16][128];   // transposed A tile: As[k][m]
    __shared__ float Bs[16][128];   // Bs[k][n]

    const int tid = threadIdx.x;
    const int bm  = blockIdx.y * 128;
    const int bn  = blockIdx.x * 128;
    const int tx  = tid & 15;       // 0..15  -> 8 cols each
    const int ty  = tid >> 4;       // 0..15  -> 8 rows each

    float acc[8][8];
#pragma unroll
    for (int i = 0; i < 8; i++)
#pragma unroll
        for (int j = 0; j < 8; j++) acc[i][j] = 0.f;

    // A tile loads: 128x16 floats = 512 float4; thread does f=tid, tid+256
    const int ar0 = tid >> 2;             // row 0..63
    const int ac  = (tid & 3) * 4;        // col 0,4,8,12
    // B tile loads: 16x128 floats = 512 float4
    const int br0 = tid >> 5;             // row 0..7
    const int bc  = (tid & 31) * 4;       // col 0..124

    for (int k0 = 0; k0 < K; k0 += 16) {
#pragma unroll
        for (int s = 0; s < 2; s++) {
            int row = ar0 + s * 64;
            float4 a = *(const float4*)&A[(size_t)(bm + row) * K + k0 + ac];
            As[ac + 0][row] = a.x;
            As[ac + 1][row] = a.y;
            As[ac + 2][row] = a.z;
            As[ac + 3][row] = a.w;
        }
#pragma unroll
        for (int s = 0; s < 2; s++) {
            int row = br0 + s * 8;
            *(float4*)&Bs[row][bc] =
                *(const float4*)&B[(size_t)(k0 + row) * N + bn + bc];
        }
        __syncthreads();

#pragma unroll
        for (int kk = 0; kk < 16; kk++) {
            float a[8], b[8];
            *(float4*)&a[0] = *(const float4*)&As[kk][ty * 8];
            *(float4*)&a[4] = *(const float4*)&As[kk][ty * 8 + 4];
            *(float4*)&b[0] = *(const float4*)&Bs[kk][tx * 8];
            *(float4*)&b[4] = *(const float4*)&Bs[kk][tx * 8 + 4];
#pragma unroll
            for (int i = 0; i < 8; i++)
#pragma unroll
                for (int j = 0; j < 8; j++)
                    acc[i][j] += a[i] * b[j];
        }
        __syncthreads();
    }

    // Epilogue (optionally + bias)
    float bv[8];
    if (bias) {
#pragma unroll
        for (int j = 0; j < 8; j++) bv[j] = bias[bn + tx * 8 + j];
    } else {
#pragma unroll
        for (int j = 0; j < 8; j++) bv[j] = 0.f;
    }
#pragma unroll
    for (int i = 0; i < 8; i++) {
        int row = bm + ty * 8 + i;
#pragma unroll
        for (int j4 = 0; j4 < 2; j4++) {
            int col = bn + tx * 8 + j4 * 4;
            float4 o;
            o.x = acc[i][j4 * 4 + 0] + bv[j4 * 4 + 0];
            o.y = acc[i][j4 * 4 + 1] + bv[j4 * 4 + 1];
            o.z = acc[i][j4 * 4 + 2] + bv[j4 * 4 + 2];
            o.w = acc[i][j4 * 4 + 3] + bv[j4 * 4 + 3];
            *(float4*)&C[(size_t)row * N + col] = o;
        }
    }
}

// ---------------------------------------------------------------------------
// Window attention: one block per (window, head, batch).
// grid = (64 windows, 8 heads, 32 batch), 128 threads.
// ---------------------------------------------------------------------------
__global__ __launch_bounds__(128) void attn_kernel(
    const float* __restrict__ qkv,      // [M_TOK, 768]
    const float* __restrict__ pos_emb,  // [13,13]
    float* __restrict__ out)            // [M_TOK, 256]
{
    __shared__ float q[NT][HD];
    __shared__ float k[NT][HD];
    __shared__ float v[NT][HD];
    __shared__ float S[NT][53];         // padded, odd stride -> conflict-free cols
    __shared__ float pos[169];
    __shared__ int   rowbase[NT];

    const int tid = threadIdx.x;
    const int w = blockIdx.x;   // window index (wr*8 + wc)
    const int h = blockIdx.y;
    const int b = blockIdx.z;
    const int wr = w >> 3, wc = w & 7;

    // FIX R1: blockDim=128 < 169 — must loop, not predicate once.
    for (int p = tid; p < 169; p += 128) pos[p] = pos_emb[p];
    if (tid < NT) {
        int ty = tid / WS, tx = tid % WS;
        int y = wr * WS + ty, x = wc * WS + tx;
        rowbase[tid] = (b * 56 + y) * 56 + x;
    }
    __syncthreads();

    // Gather q/k/v tiles (vectorized 16B, coalesced per token row)
    for (int f = tid; f < NT * 8; f += 128) {
        int t = f >> 3, d4 = (f & 7) * 4;
        size_t base = (size_t)rowbase[t] * QKV_N + h * HD + d4;
        *(float4*)&q[t][d4] = *(const float4*)&qkv[base];
        *(float4*)&k[t][d4] = *(const float4*)&qkv[base + 256];
        *(float4*)&v[t][d4] = *(const float4*)&qkv[base + 512];
    }
    __syncthreads();

    // Scores: S[i][j] = scale * <q_i, k_j> + bias(i,j)
    for (int e = tid; e < NT * NT; e += 128) {
        int i = e / NT, j = e - i * NT;
        const float4* qi = (const float4*)q[i];
        const float4* kj = (const float4*)k[j];
        float dot = 0.f;
#pragma unroll
        for (int d = 0; d < 8; d++) {
            float4 a = qi[d], c = kj[d];
            dot += a.x * c.x + a.y * c.y + a.z * c.z + a.w * c.w;
        }
        int dx = j / WS - i / WS + 6;
        int dy = j % WS - i % WS + 6;
        S[i][j] = dot * SCALE + pos[dx * 13 + dy];
    }
    __syncthreads();

    // Row softmax (one thread per row)
    if (tid < NT) {
        float m = -1e30f;
#pragma unroll
        for (int j = 0; j < NT; j++) m = fmaxf(m, S[tid][j]);
        float s = 0.f;
#pragma unroll
        for (int j = 0; j < NT; j++) {
            float e = __expf(S[tid][j] - m);
            S[tid][j] = e;
            s += e;
        }
        float inv = 1.f / s;
#pragma unroll
        for (int j = 0; j < NT; j++) S[tid][j] *= inv;
    }
    __syncthreads();

    // O = P @ V, scatter to [M_TOK, 256] at channel h*32+d
    for (int f = tid; f < NT * 8; f += 128) {
        int i = f >> 3, d4 = (f & 7) * 4;
        float4 acc = make_float4(0.f, 0.f, 0.f, 0.f);
#pragma unroll
        for (int j = 0; j < NT; j++) {
            float p = S[i][j];
            float4 vv = *(const float4*)&v[j][d4];
            acc.x += p * vv.x;
            acc.y += p * vv.y;
            acc.z += p * vv.z;
            acc.w += p * vv.w;
        }
        *(float4*)&out[(size_t)rowbase[i] * DIM + h * HD + d4] = acc;
    }
}

// ---------------------------------------------------------------------------
extern "C" void kernel_launch(void* const* d_in, const int* in_sizes, int n_in,
                              void* d_out, int out_size)
{
    const float* x      = (const float*)d_in[0];
    const float* w_qkv  = (const float*)d_in[1];
    const float* w_out  = (const float*)d_in[2];
    const float* b_out  = (const float*)d_in[3];
    const float* pos    = (const float*)d_in[4];
    float* out = (float*)d_out;

    float* qkv_ptr = nullptr;
    float* attn_ptr = nullptr;
    cudaGetSymbolAddress((void**)&qkv_ptr, g_qkv);
    cudaGetSymbolAddress((void**)&attn_ptr, g_attn);

    // 1) qkv = x @ w_qkv       [100352,256] @ [256,768]
    {
        dim3 grid(QKV_N / 128, M_TOK / 128);
        sgemm_kernel<<<grid, 256>>>(x, w_qkv, qkv_ptr, nullptr, QKV_N, DIM);
    }
    // 2) window attention -> g_attn [100352,256]
    {
        dim3 grid(64, HEADS, 32);
        attn_kernel<<<grid, 128>>>(qkv_ptr, pos, attn_ptr);
    }
    // 3) out = g_attn @ w_out + b_out   [100352,256] @ [256,256]
    {
        dim3 grid(DIM / 128, M_TOK / 128);
        sgemm_kernel<<<grid, 256>>>(attn_ptr, w_out, out, b_out, DIM, DIM);
    }
}

// round 3
// speedup vs baseline: 1.5910x; 1.5910x over previous
#include <cuda_runtime.h>

#define M_TOK   100352      // 32 * 56 * 56
#define DIM     256
#define QKV_N   768
#define HEADS   8
#define HD      32
#define WS      7
#define NT      49          // tokens per window
#define SCALE   0.17677669529663687f  // 32^-0.5

#define NP 52               // tokens padded to 4
#define QS 36               // q,v row stride (floats)
#define KS 56               // kT row stride
#define SS 53               // S row stride (odd -> conflict-free rows)

// Scratch (device globals: allocation-free per harness rules)
__device__ float g_qkv[(size_t)M_TOK * QKV_N];   // 308 MB
__device__ float g_attn[(size_t)M_TOK * DIM];    // 103 MB
__device__ float g_bias[NT * NT];                // 49x49 precomputed rel-pos bias

// ---------------------------------------------------------------------------
// Classic 128x128x16 SGEMM, 256 threads, 8x8 per-thread micro-tile.
// ---------------------------------------------------------------------------
__global__ __launch_bounds__(256) void sgemm_kernel(
    const float* __restrict__ A, const float* __restrict__ B,
    float* __restrict__ C, const float* __restrict__ bias,
    int N, int K)
{
    __shared__ float As[16][128];   // transposed A tile: As[k][m]
    __shared__ float Bs[16][128];   // Bs[k][n]

    const int tid = threadIdx.x;
    const int bm  = blockIdx.y * 128;
    const int bn  = blockIdx.x * 128;
    const int tx  = tid & 15;
    const int ty  = tid >> 4;

    float acc[8][8];
#pragma unroll
    for (int i = 0; i < 8; i++)
#pragma unroll
        for (int j = 0; j < 8; j++) acc[i][j] = 0.f;

    const int ar0 = tid >> 2;
    const int ac  = (tid & 3) * 4;
    const int br0 = tid >> 5;
    const int bc  = (tid & 31) * 4;

    for (int k0 = 0; k0 < K; k0 += 16) {
#pragma unroll
        for (int s = 0; s < 2; s++) {
            int row = ar0 + s * 64;
            float4 a = *(const float4*)&A[(size_t)(bm + row) * K + k0 + ac];
            As[ac + 0][row] = a.x;
            As[ac + 1][row] = a.y;
            As[ac + 2][row] = a.z;
            As[ac + 3][row] = a.w;
        }
#pragma unroll
        for (int s = 0; s < 2; s++) {
            int row = br0 + s * 8;
            *(float4*)&Bs[row][bc] =
                *(const float4*)&B[(size_t)(k0 + row) * N + bn + bc];
        }
        __syncthreads();

#pragma unroll
        for (int kk = 0; kk < 16; kk++) {
            float a[8], b[8];
            *(float4*)&a[0] = *(const float4*)&As[kk][ty * 8];
            *(float4*)&a[4] = *(const float4*)&As[kk][ty * 8 + 4];
            *(float4*)&b[0] = *(const float4*)&Bs[kk][tx * 8];
            *(float4*)&b[4] = *(const float4*)&Bs[kk][tx * 8 + 4];
#pragma unroll
            for (int i = 0; i < 8; i++)
#pragma unroll
                for (int j = 0; j < 8; j++)
                    acc[i][j] += a[i] * b[j];
        }
        __syncthreads();
    }

    float bv[8];
    if (bias) {
#pragma unroll
        for (int j = 0; j < 8; j++) bv[j] = bias[bn + tx * 8 + j];
    } else {
#pragma unroll
        for (int j = 0; j < 8; j++) bv[j] = 0.f;
    }
#pragma unroll
    for (int i = 0; i < 8; i++) {
        int row = bm + ty * 8 + i;
#pragma unroll
        for (int j4 = 0; j4 < 2; j4++) {
            int col = bn + tx * 8 + j4 * 4;
            float4 o;
            o.x = acc[i][j4 * 4 + 0] + bv[j4 * 4 + 0];
            o.y = acc[i][j4 * 4 + 1] + bv[j4 * 4 + 1];
            o.z = acc[i][j4 * 4 + 2] + bv[j4 * 4 + 2];
            o.w = acc[i][j4 * 4 + 3] + bv[j4 * 4 + 3];
            *(float4*)&C[(size_t)row * N + col] = o;
        }
    }
}

// ---------------------------------------------------------------------------
// Precompute relative-position bias table bias[i][j] (block-invariant).
// ---------------------------------------------------------------------------
__global__ void bias_kernel(const float* __restrict__ pos_emb,
                            float* __restrict__ biasG)
{
    int e = blockIdx.x * 256 + threadIdx.x;
    if (e < NT * NT) {
        int i = e / NT, j = e - i * NT;
        int dx = j / WS - i / WS + (WS - 1);
        int dy = j % WS - i % WS + (WS - 1);
        biasG[e] = pos_emb[dx * (2 * WS - 1) + dy];
    }
}

// ---------------------------------------------------------------------------
// Window attention v2: register-blocked 4x4 tiles, one block per
// (window, head, batch). grid = (64, 8, 32), 128 threads.
// ---------------------------------------------------------------------------
__global__ __launch_bounds__(128) void attn_kernel(
    const float* __restrict__ qkv,      // [M_TOK, 768]
    const float* __restrict__ biasG,    // [49*49]
    float* __restrict__ out)            // [M_TOK, 256]
{
    __shared__ float q[NP][QS];         // [i][d]  (rows 49..51 garbage, unread results)
    __shared__ float kT[HD][KS];        // [d][j]
    __shared__ float v[NT][QS];         // [j][d]
    __shared__ float S[NP][SS];         // scores/probs
    __shared__ float bias_s[NT * NT];
    __shared__ int   rowbase[NT];

    const int tid = threadIdx.x;
    const int w = blockIdx.x;
    const int h = blockIdx.y;
    const int b = blockIdx.z;
    const int wr = w >> 3, wc = w & 7;

    if (tid < NT) {
        int ty = tid / WS, tx = tid - ty * WS;
        rowbase[tid] = (b * 56 + wr * WS + ty) * 56 + wc * WS + tx;
    }
    for (int p = tid; p < NT * NT; p += 128) bias_s[p] = biasG[p];
    __syncthreads();

    // Gather q/k/v (k transposed into kT)
    for (int f = tid; f < NT * 8; f += 128) {
        int t = f >> 3, d4 = (f & 7) * 4;
        size_t base = (size_t)rowbase[t] * QKV_N + h * HD + d4;
        float4 qq = *(const float4*)&qkv[base];
        float4 kk = *(const float4*)&qkv[base + 256];
        float4 vv = *(const float4*)&qkv[base + 512];
        *(float4*)&q[t][d4] = qq;
        kT[d4 + 0][t] = kk.x;
        kT[d4 + 1][t] = kk.y;
        kT[d4 + 2][t] = kk.z;
        kT[d4 + 3][t] = kk.w;
        *(float4*)&v[t][d4] = vv;
    }
    __syncthreads();

    // Scores: 13x13 grid of 4x4 tiles, outer-product over d (8 LDS.128 / 64 FMA)
    for (int T = tid; T < 169; T += 128) {
        int it = T % 13, jt = T / 13;
        int i0 = it * 4, j0 = jt * 4;
        float acc[4][4] = {};
#pragma unroll
        for (int d4 = 0; d4 < HD; d4 += 4) {
            float4 a[4], kk[4];
#pragma unroll
            for (int r = 0; r < 4; r++) a[r] = *(const float4*)&q[i0 + r][d4];
#pragma unroll
            for (int c = 0; c < 4; c++) kk[c] = *(const float4*)&kT[d4 + c][j0];
#pragma unroll
            for (int r = 0; r < 4; r++) {
                acc[r][0] += a[r].x * kk[0].x + a[r].y * kk[1].x + a[r].z * kk[2].x + a[r].w * kk[3].x;
                acc[r][1] += a[r].x * kk[0].y + a[r].y * kk[1].y + a[r].z * kk[2].y + a[r].w * kk[3].y;
                acc[r][2] += a[r].x * kk[0].z + a[r].y * kk[1].z + a[r].z * kk[2].z + a[r].w * kk[3].z;
                acc[r][3] += a[r].x * kk[0].w + a[r].y * kk[1].w + a[r].z * kk[2].w + a[r].w * kk[3].w;
            }
        }
#pragma unroll
        for (int r = 0; r < 4; r++)
#pragma unroll
            for (int c = 0; c < 4; c++)
                S[i0 + r][j0 + c] = acc[r][c];
    }
    __syncthreads();

    // Softmax rows (scale + bias folded in here; bias from smem)
    if (tid < NT) {
        float* row = S[tid];
        const float* brow = &bias_s[tid * NT];
        float m = -1e30f;
#pragma unroll
        for (int j = 0; j < NT; j++) {
            float t = row[j] * SCALE + brow[j];
            row[j] = t;
            m = fmaxf(m, t);
        }
        float s = 0.f;
#pragma unroll
        for (int j = 0; j < NT; j++) {
            float e = __expf(row[j] - m);
            row[j] = e;
            s += e;
        }
        float inv = 1.f / s;
#pragma unroll
        for (int j = 0; j < NT; j++) row[j] *= inv;
    }
    __syncthreads();

    // PV: 13 i-tiles x 8 d-tiles, 4 rows x float4 per thread-tile
    for (int T = tid; T < 104; T += 128) {
        int it = T % 13, dt = T / 13;
        int i0 = it * 4, d0 = dt * 4;
        float4 acc0 = {0, 0, 0, 0}, acc1 = {0, 0, 0, 0};
        float4 acc2 = {0, 0, 0, 0}, acc3 = {0, 0, 0, 0};
        for (int j = 0; j < NT; j++) {
            float4 vv = *(const float4*)&v[j][d0];
            float s0 = S[i0 + 0][j];
            float s1 = S[i0 + 1][j];
            float s2 = S[i0 + 2][j];
            float s3 = S[i0 + 3][j];
            acc0.x += s0 * vv.x; acc0.y += s0 * vv.y; acc0.z += s0 * vv.z; acc0.w += s0 * vv.w;
            acc1.x += s1 * vv.x; acc1.y += s1 * vv.y; acc1.z += s1 * vv.z; acc1.w += s1 * vv.w;
            acc2.x += s2 * vv.x; acc2.y += s2 * vv.y; acc2.z += s2 * vv.z; acc2.w += s2 * vv.w;
            acc3.x += s3 * vv.x; acc3.y += s3 * vv.y; acc3.z += s3 * vv.z; acc3.w += s3 * vv.w;
        }
        float4 accs[4] = {acc0, acc1, acc2, acc3};
#pragma unroll
        for (int r = 0; r < 4; r++) {
            if (i0 + r < NT)
                *(float4*)&out[(size_t)rowbase[i0 + r] * DIM + h * HD + d0] = accs[r];
        }
    }
}

// ---------------------------------------------------------------------------
extern "C" void kernel_launch(void* const* d_in, const int* in_sizes, int n_in,
                              void* d_out, int out_size)
{
    const float* x      = (const float*)d_in[0];
    const float* w_qkv  = (const float*)d_in[1];
    const float* w_out  = (const float*)d_in[2];
    const float* b_out  = (const float*)d_in[3];
    const float* pos    = (const float*)d_in[4];
    float* out = (float*)d_out;

    float* qkv_ptr = nullptr;
    float* attn_ptr = nullptr;
    float* bias_ptr = nullptr;
    cudaGetSymbolAddress((void**)&qkv_ptr, g_qkv);
    cudaGetSymbolAddress((void**)&attn_ptr, g_attn);
    cudaGetSymbolAddress((void**)&bias_ptr, g_bias);

    // 0) precompute rel-pos bias table (2401 entries)
    bias_kernel<<<(NT * NT + 255) / 256, 256>>>(pos, bias_ptr);

    // 1) qkv = x @ w_qkv       [100352,256] @ [256,768]
    {
        dim3 grid(QKV_N / 128, M_TOK / 128);
        sgemm_kernel<<<grid, 256>>>(x, w_qkv, qkv_ptr, nullptr, QKV_N, DIM);
    }
    // 2) window attention -> g_attn [100352,256]
    {
        dim3 grid(64, HEADS, 32);
        attn_kernel<<<grid, 128>>>(qkv_ptr, bias_ptr, attn_ptr);
    }
    // 3) out = g_attn @ w_out + b_out   [100352,256] @ [256,256]
    {
        dim3 grid(DIM / 128, M_TOK / 128);
        sgemm_kernel<<<grid, 256>>>(attn_ptr, w_out, out, b_out, DIM, DIM);
    }
}

// round 5
// speedup vs baseline: 2.4663x; 1.5502x over previous
#include <cuda_runtime.h>
#include <cstdint>

#define M_TOK   100352      // 32 * 56 * 56
#define DIM     256
#define QKV_N   768
#define HEADS   8
#define HD      32
#define WS      7
#define NT      49
#define SCALE   0.17677669529663687f

#define NP 52
#define QS 36
#define KS 56
#define SS 53

// Scratch (device globals: allocation-free per harness rules)
__device__ float g_qkv[(size_t)M_TOK * QKV_N];   // 308 MB
__device__ float g_attn[(size_t)M_TOK * DIM];    // 103 MB
__device__ float g_bias[NT * NT];
__device__ float g_wqkvT[QKV_N * DIM];           // [768][256] transposed w_qkv
__device__ float g_woutT[DIM * DIM];             // [256][256] transposed w_out

__device__ __forceinline__ uint32_t f2tf32(float f) {
    uint32_t r;
    asm("cvt.rna.tf32.f32 %0, %1;" : "=r"(r) : "f"(f));
    return r;
}

// ---------------------------------------------------------------------------
// tf32 mma.sync GEMM: C[M,N] = A[M,K] @ BT[N,K]^T (+bias).
// 128x128 block tile, 8 warps (2x4), 64x32 warp tiles, K-chunk 32,
// register-staged double buffer. K % 32 == 0, M,N % 128 == 0.
// Smem stride 36 floats: fragment LDS bank = (4*row+col)&31 -> conflict-free.
// ---------------------------------------------------------------------------
#define TSTR 36
#define TILEF (128 * TSTR)          // floats per tile buffer

__global__ __launch_bounds__(256) void mma_gemm(
    const float* __restrict__ A, const float* __restrict__ BT,
    float* __restrict__ C, const float* __restrict__ bias,
    int N, int K)
{
    extern __shared__ float sm[];
    // layout: As0 | Bs0 | As1 | Bs1
    float* Asb[2] = { sm,             sm + 2 * TILEF };
    float* Bsb[2] = { sm + TILEF,     sm + 3 * TILEF };

    const int tid  = threadIdx.x;
    const int wid  = tid >> 5;
    const int lane = tid & 31;
    const int group = lane >> 2;
    const int tig   = lane & 3;
    const int warp_m = wid & 1;          // 0..1
    const int warp_n = wid >> 1;         // 0..3
    const int m0w = warp_m * 64;
    const int n0w = warp_n * 32;
    const int bm = blockIdx.y * 128;
    const int bn = blockIdx.x * 128;

    // loader mapping: float4 f = tid + i*256 -> row = f>>3, colf4 = tid&7
    const int lrow = tid >> 3;           // 0..31
    const int lcf4 = tid & 7;            // 0..7

    float c[4][4][4];
#pragma unroll
    for (int mt = 0; mt < 4; mt++)
#pragma unroll
        for (int nt = 0; nt < 4; nt++)
#pragma unroll
            for (int r = 0; r < 4; r++) c[mt][nt][r] = 0.f;

    float4 pa[4], pb[4];

    // prologue: LDG chunk 0
#pragma unroll
    for (int i = 0; i < 4; i++) {
        const int row = lrow + i * 32;
        pa[i] = *(const float4*)&A [(size_t)(bm + row) * K + lcf4 * 4];
        pb[i] = *(const float4*)&BT[(size_t)(bn + row) * K + lcf4 * 4];
    }
    // STS chunk 0 (tf32 converted, float2 stores: 8B-aligned for stride 36)
#pragma unroll
    for (int i = 0; i < 4; i++) {
        const int row = lrow + i * 32;
        float* pA = &Asb[0][row * TSTR + lcf4 * 4];
        float* pB = &Bsb[0][row * TSTR + lcf4 * 4];
        ((float2*)pA)[0] = make_float2(__uint_as_float(f2tf32(pa[i].x)),
                                       __uint_as_float(f2tf32(pa[i].y)));
        ((float2*)pA)[1] = make_float2(__uint_as_float(f2tf32(pa[i].z)),
                                       __uint_as_float(f2tf32(pa[i].w)));
        ((float2*)pB)[0] = make_float2(__uint_as_float(f2tf32(pb[i].x)),
                                       __uint_as_float(f2tf32(pb[i].y)));
        ((float2*)pB)[1] = make_float2(__uint_as_float(f2tf32(pb[i].z)),
                                       __uint_as_float(f2tf32(pb[i].w)));
    }
    __syncthreads();

    const int nch = K >> 5;
    for (int cidx = 0; cidx < nch; cidx++) {
        const int buf = cidx & 1;
        const bool more = (cidx + 1 < nch);
        if (more) {
            const int k0 = (cidx + 1) * 32;
#pragma unroll
            for (int i = 0; i < 4; i++) {
                const int row = lrow + i * 32;
                pa[i] = *(const float4*)&A [(size_t)(bm + row) * K + k0 + lcf4 * 4];
                pb[i] = *(const float4*)&BT[(size_t)(bn + row) * K + k0 + lcf4 * 4];
            }
        }

        const uint32_t* As = (const uint32_t*)Asb[buf];
        const uint32_t* Bs = (const uint32_t*)Bsb[buf];
#pragma unroll
        for (int k8 = 0; k8 < 4; k8++) {
            const int kc = k8 * 8 + tig;
            uint32_t a[4][4], b[4][2];
#pragma unroll
            for (int mt = 0; mt < 4; mt++) {
                const int r0 = m0w + mt * 16 + group;
                a[mt][0] = As[r0 * TSTR + kc];
                a[mt][1] = As[(r0 + 8) * TSTR + kc];
                a[mt][2] = As[r0 * TSTR + kc + 4];
                a[mt][3] = As[(r0 + 8) * TSTR + kc + 4];
            }
#pragma unroll
            for (int nt = 0; nt < 4; nt++) {
                const int r0 = n0w + nt * 8 + group;
                b[nt][0] = Bs[r0 * TSTR + kc];
                b[nt][1] = Bs[r0 * TSTR + kc + 4];
            }
#pragma unroll
            for (int mt = 0; mt < 4; mt++)
#pragma unroll
                for (int nt = 0; nt < 4; nt++) {
                    asm volatile(
                        "mma.sync.aligned.m16n8k8.row.col.f32.tf32.tf32.f32 "
                        "{%0,%1,%2,%3}, {%4,%5,%6,%7}, {%8,%9}, {%0,%1,%2,%3};"
                        : "+f"(c[mt][nt][0]), "+f"(c[mt][nt][1]),
                          "+f"(c[mt][nt][2]), "+f"(c[mt][nt][3])
                        : "r"(a[mt][0]), "r"(a[mt][1]), "r"(a[mt][2]), "r"(a[mt][3]),
                          "r"(b[nt][0]), "r"(b[nt][1]));
                }
        }

        if (more) {
            const int nb = buf ^ 1;
#pragma unroll
            for (int i = 0; i < 4; i++) {
                const int row = lrow + i * 32;
                float* pA = &Asb[nb][row * TSTR + lcf4 * 4];
                float* pB = &Bsb[nb][row * TSTR + lcf4 * 4];
                ((float2*)pA)[0] = make_float2(__uint_as_float(f2tf32(pa[i].x)),
                                               __uint_as_float(f2tf32(pa[i].y)));
                ((float2*)pA)[1] = make_float2(__uint_as_float(f2tf32(pa[i].z)),
                                               __uint_as_float(f2tf32(pa[i].w)));
                ((float2*)pB)[0] = make_float2(__uint_as_float(f2tf32(pb[i].x)),
                                               __uint_as_float(f2tf32(pb[i].y)));
                ((float2*)pB)[1] = make_float2(__uint_as_float(f2tf32(pb[i].z)),
                                               __uint_as_float(f2tf32(pb[i].w)));
            }
            __syncthreads();
        }
    }

    // Epilogue
#pragma unroll
    for (int nt = 0; nt < 4; nt++) {
        const int col = bn + n0w + nt * 8 + tig * 2;
        float bv0 = 0.f, bv1 = 0.f;
        if (bias) { bv0 = bias[col]; bv1 = bias[col + 1]; }
#pragma unroll
        for (int mt = 0; mt < 4; mt++) {
            const int row = bm + m0w + mt * 16 + group;
            float2 v0 = make_float2(c[mt][nt][0] + bv0, c[mt][nt][1] + bv1);
            float2 v1 = make_float2(c[mt][nt][2] + bv0, c[mt][nt][3] + bv1);
            *(float2*)&C[(size_t)row * N + col]       = v0;
            *(float2*)&C[(size_t)(row + 8) * N + col] = v1;
        }
    }
}

// ---------------------------------------------------------------------------
// Weight transpose: WT[n][k] = W[k][n]
// ---------------------------------------------------------------------------
__global__ void transpose_kernel(const float* __restrict__ W,
                                 float* __restrict__ WT, int R, int Cc)
{
    __shared__ float t[32][33];
    int x = blockIdx.x * 32 + threadIdx.x;
    int y = blockIdx.y * 32 + threadIdx.y;
    if (x < Cc && y < R) t[threadIdx.y][threadIdx.x] = W[y * Cc + x];
    __syncthreads();
    x = blockIdx.y * 32 + threadIdx.x;
    y = blockIdx.x * 32 + threadIdx.y;
    if (x < R && y < Cc) WT[y * R + x] = t[threadIdx.x][threadIdx.y];
}

// ---------------------------------------------------------------------------
// Precompute relative-position bias table bias[i][j].
// ---------------------------------------------------------------------------
__global__ void bias_kernel(const float* __restrict__ pos_emb,
                            float* __restrict__ biasG)
{
    int e = blockIdx.x * 256 + threadIdx.x;
    if (e < NT * NT) {
        int i = e / NT, j = e - i * NT;
        int dx = j / WS - i / WS + (WS - 1);
        int dy = j % WS - i % WS + (WS - 1);
        biasG[e] = pos_emb[dx * (2 * WS - 1) + dy];
    }
}

// ---------------------------------------------------------------------------
// Window attention: register-blocked 4x4 tiles, block per (window, head, batch)
// ---------------------------------------------------------------------------
__global__ __launch_bounds__(128) void attn_kernel(
    const float* __restrict__ qkv,
    const float* __restrict__ biasG,
    float* __restrict__ out)
{
    __shared__ float q[NP][QS];
    __shared__ float kT[HD][KS];
    __shared__ float v[NT][QS];
    __shared__ float S[NP][SS];
    __shared__ float bias_s[NT * NT];
    __shared__ int   rowbase[NT];

    const int tid = threadIdx.x;
    const int w = blockIdx.x;
    const int h = blockIdx.y;
    const int b = blockIdx.z;
    const int wr = w >> 3, wc = w & 7;

    if (tid < NT) {
        int ty = tid / WS, tx = tid - ty * WS;
        rowbase[tid] = (b * 56 + wr * WS + ty) * 56 + wc * WS + tx;
    }
    for (int p = tid; p < NT * NT; p += 128) bias_s[p] = biasG[p];
    __syncthreads();

    for (int f = tid; f < NT * 8; f += 128) {
        int t = f >> 3, d4 = (f & 7) * 4;
        size_t base = (size_t)rowbase[t] * QKV_N + h * HD + d4;
        float4 qq = *(const float4*)&qkv[base];
        float4 kk = *(const float4*)&qkv[base + 256];
        float4 vv = *(const float4*)&qkv[base + 512];
        *(float4*)&q[t][d4] = qq;
        kT[d4 + 0][t] = kk.x;
        kT[d4 + 1][t] = kk.y;
        kT[d4 + 2][t] = kk.z;
        kT[d4 + 3][t] = kk.w;
        *(float4*)&v[t][d4] = vv;
    }
    __syncthreads();

    for (int T = tid; T < 169; T += 128) {
        int it = T % 13, jt = T / 13;
        int i0 = it * 4, j0 = jt * 4;
        float acc[4][4] = {};
#pragma unroll
        for (int d4 = 0; d4 < HD; d4 += 4) {
            float4 a[4], kk[4];
#pragma unroll
            for (int r = 0; r < 4; r++) a[r] = *(const float4*)&q[i0 + r][d4];
#pragma unroll
            for (int c = 0; c < 4; c++) kk[c] = *(const float4*)&kT[d4 + c][j0];
#pragma unroll
            for (int r = 0; r < 4; r++) {
                acc[r][0] += a[r].x * kk[0].x + a[r].y * kk[1].x + a[r].z * kk[2].x + a[r].w * kk[3].x;
                acc[r][1] += a[r].x * kk[0].y + a[r].y * kk[1].y + a[r].z * kk[2].y + a[r].w * kk[3].y;
                acc[r][2] += a[r].x * kk[0].z + a[r].y * kk[1].z + a[r].z * kk[2].z + a[r].w * kk[3].z;
                acc[r][3] += a[r].x * kk[0].w + a[r].y * kk[1].w + a[r].z * kk[2].w + a[r].w * kk[3].w;
            }
        }
#pragma unroll
        for (int r = 0; r < 4; r++)
#pragma unroll
            for (int c = 0; c < 4; c++)
                S[i0 + r][j0 + c] = acc[r][c];
    }
    __syncthreads();

    if (tid < NT) {
        float* row = S[tid];
        const float* brow = &bias_s[tid * NT];
        float m = -1e30f;
#pragma unroll
        for (int j = 0; j < NT; j++) {
            float t = row[j] * SCALE + brow[j];
            row[j] = t;
            m = fmaxf(m, t);
        }
        float s = 0.f;
#pragma unroll
        for (int j = 0; j < NT; j++) {
            float e = __expf(row[j] - m);
            row[j] = e;
            s += e;
        }
        float inv = 1.f / s;
#pragma unroll
        for (int j = 0; j < NT; j++) row[j] *= inv;
    }
    __syncthreads();

    for (int T = tid; T < 104; T += 128) {
        int it = T % 13, dt = T / 13;
        int i0 = it * 4, d0 = dt * 4;
        float4 acc0 = {0,0,0,0}, acc1 = {0,0,0,0}, acc2 = {0,0,0,0}, acc3 = {0,0,0,0};
        for (int j = 0; j < NT; j++) {
            float4 vv = *(const float4*)&v[j][d0];
            float s0 = S[i0 + 0][j], s1 = S[i0 + 1][j];
            float s2 = S[i0 + 2][j], s3 = S[i0 + 3][j];
            acc0.x += s0 * vv.x; acc0.y += s0 * vv.y; acc0.z += s0 * vv.z; acc0.w += s0 * vv.w;
            acc1.x += s1 * vv.x; acc1.y += s1 * vv.y; acc1.z += s1 * vv.z; acc1.w += s1 * vv.w;
            acc2.x += s2 * vv.x; acc2.y += s2 * vv.y; acc2.z += s2 * vv.z; acc2.w += s2 * vv.w;
            acc3.x += s3 * vv.x; acc3.y += s3 * vv.y; acc3.z += s3 * vv.z; acc3.w += s3 * vv.w;
        }
        float4 accs[4] = {acc0, acc1, acc2, acc3};
#pragma unroll
        for (int r = 0; r < 4; r++) {
            if (i0 + r < NT)
                *(float4*)&out[(size_t)rowbase[i0 + r] * DIM + h * HD + d0] = accs[r];
        }
    }
}

// ---------------------------------------------------------------------------
extern "C" void kernel_launch(void* const* d_in, const int* in_sizes, int n_in,
                              void* d_out, int out_size)
{
    const float* x      = (const float*)d_in[0];
    const float* w_qkv  = (const float*)d_in[1];
    const float* w_out  = (const float*)d_in[2];
    const float* b_out  = (const float*)d_in[3];
    const float* pos    = (const float*)d_in[4];
    float* out = (float*)d_out;

    float *qkv_ptr, *attn_ptr, *bias_ptr, *wqkvT_ptr, *woutT_ptr;
    cudaGetSymbolAddress((void**)&qkv_ptr,  g_qkv);
    cudaGetSymbolAddress((void**)&attn_ptr, g_attn);
    cudaGetSymbolAddress((void**)&bias_ptr, g_bias);
    cudaGetSymbolAddress((void**)&wqkvT_ptr, g_wqkvT);
    cudaGetSymbolAddress((void**)&woutT_ptr, g_woutT);

    const int SMEM_BYTES = 4 * TILEF * (int)sizeof(float);   // 73728
    static bool attr_set = false;
    if (!attr_set) {
        cudaFuncSetAttribute(mma_gemm,
            cudaFuncAttributeMaxDynamicSharedMemorySize, SMEM_BYTES);
        attr_set = true;
    }

    // 0) prep: bias table + weight transposes (tiny)
    bias_kernel<<<(NT * NT + 255) / 256, 256>>>(pos, bias_ptr);
    {
        dim3 blk(32, 32);
        transpose_kernel<<<dim3(QKV_N / 32, DIM / 32), blk>>>(w_qkv, wqkvT_ptr, DIM, QKV_N);
        transpose_kernel<<<dim3(DIM / 32, DIM / 32), blk>>>(w_out, woutT_ptr, DIM, DIM);
    }

    // 1) qkv = x @ w_qkv   (tf32 mma.sync)
    {
        dim3 grid(QKV_N / 128, M_TOK / 128);
        mma_gemm<<<grid, 256, SMEM_BYTES>>>(x, wqkvT_ptr, qkv_ptr, nullptr, QKV_N, DIM);
    }
    // 2) window attention
    {
        dim3 grid(64, HEADS, 32);
        attn_kernel<<<grid, 128>>>(qkv_ptr, bias_ptr, attn_ptr);
    }
    // 3) out = attn @ w_out + b_out   (tf32 mma.sync)
    {
        dim3 grid(DIM / 128, M_TOK / 128);
        mma_gemm<<<grid, 256, SMEM_BYTES>>>(attn_ptr, woutT_ptr, out, b_out, DIM, DIM);
    }
}

// round 6
// speedup vs baseline: 3.1242x; 1.2667x over previous
#include <cuda_runtime.h>
#include <cstdint>

#define M_TOK   100352      // 32 * 56 * 56
#define DIM     256
#define QKV_N   768
#define HEADS   8
#define HD      32
#define WS      7
#define NT      49
#define SCALE   0.17677669529663687f

#define NP 52
#define QS 36
#define KS 56
#define SS 53

// Scratch (device globals: allocation-free per harness rules)
__device__ float g_qkv[(size_t)M_TOK * QKV_N];   // 308 MB
__device__ float g_attn[(size_t)M_TOK * DIM];    // 103 MB (tf32-rounded at source)
__device__ float g_xtf[(size_t)M_TOK * DIM];     // 103 MB x pre-rounded to tf32
__device__ float g_bias[NT * NT];
__device__ float g_wqkvT[QKV_N * DIM];           // transposed + tf32-rounded
__device__ float g_woutT[DIM * DIM];             // transposed + tf32-rounded

__device__ __forceinline__ uint32_t f2tf32(float f) {
    uint32_t r;
    asm("cvt.rna.tf32.f32 %0, %1;" : "=r"(r) : "f"(f));
    return r;
}
__device__ __forceinline__ uint32_t smem_u32(const void* p) {
    uint32_t a;
    asm("{ .reg .u64 t; cvta.to.shared.u64 t, %1; cvt.u32.u64 %0, t; }"
        : "=r"(a) : "l"(p));
    return a;
}
__device__ __forceinline__ void cpasync16(uint32_t dst, const void* src) {
    asm volatile("cp.async.ca.shared.global [%0], [%1], 16;"
                 :: "r"(dst), "l"(src));
}

// ---------------------------------------------------------------------------
// tf32 mma.sync GEMM with cp.async 2-stage pipeline.
// C[M,N] = A[M,K] @ BT[N,K]^T (+bias). A, BT pre-rounded to tf32 in global.
// 128x128 block tile, 8 warps (2x4), 64x32 warp tiles, K-chunk 32.
// __launch_bounds__(256,2) -> <=128 regs -> 2 CTAs/SM.
// ---------------------------------------------------------------------------
#define TSTR 36
#define TILEF (128 * TSTR)                 // floats per tile
#define TILEB (TILEF * 4)                  // bytes per tile

__global__ __launch_bounds__(256, 2) void mma_gemm(
    const float* __restrict__ A, const float* __restrict__ BT,
    float* __restrict__ C, const float* __restrict__ bias,
    int N, int K)
{
    extern __shared__ float sm[];
    const uint32_t smbase = smem_u32(sm);

    const int tid  = threadIdx.x;
    const int wid  = tid >> 5;
    const int lane = tid & 31;
    const int group = lane >> 2;
    const int tig   = lane & 3;
    const int m0w = (wid & 1) * 64;
    const int n0w = (wid >> 1) * 32;
    const int bm = blockIdx.y * 128;
    const int bn = blockIdx.x * 128;

    const int lrow = tid >> 3;             // 0..31
    const int lcf4 = tid & 7;              // 0..7

    float c[4][4][4];
#pragma unroll
    for (int mt = 0; mt < 4; mt++)
#pragma unroll
        for (int nt = 0; nt < 4; nt++)
#pragma unroll
            for (int r = 0; r < 4; r++) c[mt][nt][r] = 0.f;

    const int nch = K >> 5;
    const uint32_t doff0 = (uint32_t)(lrow * TSTR + lcf4 * 4) * 4;

    // issue chunk c into buffer b
    auto issue = [&](int cc, int b) {
        const int k0 = cc * 32;
        const uint32_t aBase = smbase + (uint32_t)b * 2 * TILEB + doff0;
        const uint32_t bBase = aBase + TILEB;
#pragma unroll
        for (int i = 0; i < 4; i++) {
            const int row = lrow + 32 * i;
            cpasync16(aBase + (uint32_t)i * 32 * TSTR * 4,
                      &A[(size_t)(bm + row) * K + k0 + lcf4 * 4]);
            cpasync16(bBase + (uint32_t)i * 32 * TSTR * 4,
                      &BT[(size_t)(bn + row) * K + k0 + lcf4 * 4]);
        }
    };

    issue(0, 0);
    asm volatile("cp.async.commit_group;");
    if (nch > 1) issue(1, 1);
    asm volatile("cp.async.commit_group;");

    for (int cidx = 0; cidx < nch; cidx++) {
        const int buf = cidx & 1;
        asm volatile("cp.async.wait_group 1;");
        __syncthreads();

        const uint32_t* As = (const uint32_t*)(sm + buf * 2 * TILEF);
        const uint32_t* Bs = (const uint32_t*)(sm + buf * 2 * TILEF + TILEF);
#pragma unroll
        for (int k8 = 0; k8 < 4; k8++) {
            const int kc = k8 * 8 + tig;
            uint32_t a[4][4], b[4][2];
#pragma unroll
            for (int mt = 0; mt < 4; mt++) {
                const int r0 = m0w + mt * 16 + group;
                a[mt][0] = As[r0 * TSTR + kc];
                a[mt][1] = As[(r0 + 8) * TSTR + kc];
                a[mt][2] = As[r0 * TSTR + kc + 4];
                a[mt][3] = As[(r0 + 8) * TSTR + kc + 4];
            }
#pragma unroll
            for (int nt = 0; nt < 4; nt++) {
                const int r0 = n0w + nt * 8 + group;
                b[nt][0] = Bs[r0 * TSTR + kc];
                b[nt][1] = Bs[r0 * TSTR + kc + 4];
            }
#pragma unroll
            for (int mt = 0; mt < 4; mt++)
#pragma unroll
                for (int nt = 0; nt < 4; nt++) {
                    asm volatile(
                        "mma.sync.aligned.m16n8k8.row.col.f32.tf32.tf32.f32 "
                        "{%0,%1,%2,%3}, {%4,%5,%6,%7}, {%8,%9}, {%0,%1,%2,%3};"
                        : "+f"(c[mt][nt][0]), "+f"(c[mt][nt][1]),
                          "+f"(c[mt][nt][2]), "+f"(c[mt][nt][3])
                        : "r"(a[mt][0]), "r"(a[mt][1]), "r"(a[mt][2]), "r"(a[mt][3]),
                          "r"(b[nt][0]), "r"(b[nt][1]));
                }
        }
        __syncthreads();
        if (cidx + 2 < nch) issue(cidx + 2, buf);
        asm volatile("cp.async.commit_group;");
    }

    // Epilogue
#pragma unroll
    for (int nt = 0; nt < 4; nt++) {
        const int col = bn + n0w + nt * 8 + tig * 2;
        float bv0 = 0.f, bv1 = 0.f;
        if (bias) { bv0 = bias[col]; bv1 = bias[col + 1]; }
#pragma unroll
        for (int mt = 0; mt < 4; mt++) {
            const int row = bm + m0w + mt * 16 + group;
            float2 v0 = make_float2(c[mt][nt][0] + bv0, c[mt][nt][1] + bv1);
            float2 v1 = make_float2(c[mt][nt][2] + bv0, c[mt][nt][3] + bv1);
            *(float2*)&C[(size_t)row * N + col]       = v0;
            *(float2*)&C[(size_t)(row + 8) * N + col] = v1;
        }
    }
}

// ---------------------------------------------------------------------------
// x -> tf32-rounded copy (elementwise, float4)
// ---------------------------------------------------------------------------
__global__ void tf32_round_kernel(const float* __restrict__ in,
                                  float* __restrict__ out, int n4)
{
    int i = blockIdx.x * 256 + threadIdx.x;
    if (i < n4) {
        float4 v = ((const float4*)in)[i];
        v.x = __uint_as_float(f2tf32(v.x));
        v.y = __uint_as_float(f2tf32(v.y));
        v.z = __uint_as_float(f2tf32(v.z));
        v.w = __uint_as_float(f2tf32(v.w));
        ((float4*)out)[i] = v;
    }
}

// ---------------------------------------------------------------------------
// Weight transpose + tf32 round: WT[n][k] = rna(W[k][n])
// ---------------------------------------------------------------------------
__global__ void transpose_kernel(const float* __restrict__ W,
                                 float* __restrict__ WT, int R, int Cc)
{
    __shared__ float t[32][33];
    int x = blockIdx.x * 32 + threadIdx.x;
    int y = blockIdx.y * 32 + threadIdx.y;
    if (x < Cc && y < R) t[threadIdx.y][threadIdx.x] = W[y * Cc + x];
    __syncthreads();
    x = blockIdx.y * 32 + threadIdx.x;
    y = blockIdx.x * 32 + threadIdx.y;
    if (x < R && y < Cc)
        WT[y * R + x] = __uint_as_float(f2tf32(t[threadIdx.x][threadIdx.y]));
}

// ---------------------------------------------------------------------------
// Precompute relative-position bias table bias[i][j].
// ---------------------------------------------------------------------------
__global__ void bias_kernel(const float* __restrict__ pos_emb,
                            float* __restrict__ biasG)
{
    int e = blockIdx.x * 256 + threadIdx.x;
    if (e < NT * NT) {
        int i = e / NT, j = e - i * NT;
        int dx = j / WS - i / WS + (WS - 1);
        int dy = j % WS - i % WS + (WS - 1);
        biasG[e] = pos_emb[dx * (2 * WS - 1) + dy];
    }
}

// ---------------------------------------------------------------------------
// Window attention: register-blocked 4x4 tiles, block per (window, head, batch)
// Output tf32-rounded (feeds GEMM2's cp.async path).
// ---------------------------------------------------------------------------
__global__ __launch_bounds__(128) void attn_kernel(
    const float* __restrict__ qkv,
    const float* __restrict__ biasG,
    float* __restrict__ out)
{
    __shared__ float q[NP][QS];
    __shared__ float kT[HD][KS];
    __shared__ float v[NT][QS];
    __shared__ float S[NP][SS];
    __shared__ float bias_s[NT * NT];
    __shared__ int   rowbase[NT];

    const int tid = threadIdx.x;
    const int w = blockIdx.x;
    const int h = blockIdx.y;
    const int b = blockIdx.z;
    const int wr = w >> 3, wc = w & 7;

    if (tid < NT) {
        int ty = tid / WS, tx = tid - ty * WS;
        rowbase[tid] = (b * 56 + wr * WS + ty) * 56 + wc * WS + tx;
    }
    for (int p = tid; p < NT * NT; p += 128) bias_s[p] = biasG[p];
    __syncthreads();

    for (int f = tid; f < NT * 8; f += 128) {
        int t = f >> 3, d4 = (f & 7) * 4;
        size_t base = (size_t)rowbase[t] * QKV_N + h * HD + d4;
        float4 qq = *(const float4*)&qkv[base];
        float4 kk = *(const float4*)&qkv[base + 256];
        float4 vv = *(const float4*)&qkv[base + 512];
        *(float4*)&q[t][d4] = qq;
        kT[d4 + 0][t] = kk.x;
        kT[d4 + 1][t] = kk.y;
        kT[d4 + 2][t] = kk.z;
        kT[d4 + 3][t] = kk.w;
        *(float4*)&v[t][d4] = vv;
    }
    __syncthreads();

    for (int T = tid; T < 169; T += 128) {
        int it = T % 13, jt = T / 13;
        int i0 = it * 4, j0 = jt * 4;
        float acc[4][4] = {};
#pragma unroll
        for (int d4 = 0; d4 < HD; d4 += 4) {
            float4 a[4], kk[4];
#pragma unroll
            for (int r = 0; r < 4; r++) a[r] = *(const float4*)&q[i0 + r][d4];
#pragma unroll
            for (int c = 0; c < 4; c++) kk[c] = *(const float4*)&kT[d4 + c][j0];
#pragma unroll
            for (int r = 0; r < 4; r++) {
                acc[r][0] += a[r].x * kk[0].x + a[r].y * kk[1].x + a[r].z * kk[2].x + a[r].w * kk[3].x;
                acc[r][1] += a[r].x * kk[0].y + a[r].y * kk[1].y + a[r].z * kk[2].y + a[r].w * kk[3].y;
                acc[r][2] += a[r].x * kk[0].z + a[r].y * kk[1].z + a[r].z * kk[2].z + a[r].w * kk[3].z;
                acc[r][3] += a[r].x * kk[0].w + a[r].y * kk[1].w + a[r].z * kk[2].w + a[r].w * kk[3].w;
            }
        }
#pragma unroll
        for (int r = 0; r < 4; r++)
#pragma unroll
            for (int c = 0; c < 4; c++)
                S[i0 + r][j0 + c] = acc[r][c];
    }
    __syncthreads();

    if (tid < NT) {
        float* row = S[tid];
        const float* brow = &bias_s[tid * NT];
        float m = -1e30f;
#pragma unroll
        for (int j = 0; j < NT; j++) {
            float t = row[j] * SCALE + brow[j];
            row[j] = t;
            m = fmaxf(m, t);
        }
        float s = 0.f;
#pragma unroll
        for (int j = 0; j < NT; j++) {
            float e = __expf(row[j] - m);
            row[j] = e;
            s += e;
        }
        float inv = 1.f / s;
#pragma unroll
        for (int j = 0; j < NT; j++) row[j] *= inv;
    }
    __syncthreads();

    for (int T = tid; T < 104; T += 128) {
        int it = T % 13, dt = T / 13;
        int i0 = it * 4, d0 = dt * 4;
        float4 acc0 = {0,0,0,0}, acc1 = {0,0,0,0}, acc2 = {0,0,0,0}, acc3 = {0,0,0,0};
        for (int j = 0; j < NT; j++) {
            float4 vv = *(const float4*)&v[j][d0];
            float s0 = S[i0 + 0][j], s1 = S[i0 + 1][j];
            float s2 = S[i0 + 2][j], s3 = S[i0 + 3][j];
            acc0.x += s0 * vv.x; acc0.y += s0 * vv.y; acc0.z += s0 * vv.z; acc0.w += s0 * vv.w;
            acc1.x += s1 * vv.x; acc1.y += s1 * vv.y; acc1.z += s1 * vv.z; acc1.w += s1 * vv.w;
            acc2.x += s2 * vv.x; acc2.y += s2 * vv.y; acc2.z += s2 * vv.z; acc2.w += s2 * vv.w;
            acc3.x += s3 * vv.x; acc3.y += s3 * vv.y; acc3.z += s3 * vv.z; acc3.w += s3 * vv.w;
        }
        float4 accs[4] = {acc0, acc1, acc2, acc3};
#pragma unroll
        for (int r = 0; r < 4; r++) {
            if (i0 + r < NT) {
                float4 o = accs[r];
                o.x = __uint_as_float(f2tf32(o.x));
                o.y = __uint_as_float(f2tf32(o.y));
                o.z = __uint_as_float(f2tf32(o.z));
                o.w = __uint_as_float(f2tf32(o.w));
                *(float4*)&out[(size_t)rowbase[i0 + r] * DIM + h * HD + d0] = o;
            }
        }
    }
}

// ---------------------------------------------------------------------------
extern "C" void kernel_launch(void* const* d_in, const int* in_sizes, int n_in,
                              void* d_out, int out_size)
{
    const float* x      = (const float*)d_in[0];
    const float* w_qkv  = (const float*)d_in[1];
    const float* w_out  = (const float*)d_in[2];
    const float* b_out  = (const float*)d_in[3];
    const float* pos    = (const float*)d_in[4];
    float* out = (float*)d_out;

    float *qkv_ptr, *attn_ptr, *xtf_ptr, *bias_ptr, *wqkvT_ptr, *woutT_ptr;
    cudaGetSymbolAddress((void**)&qkv_ptr,  g_qkv);
    cudaGetSymbolAddress((void**)&attn_ptr, g_attn);
    cudaGetSymbolAddress((void**)&xtf_ptr,  g_xtf);
    cudaGetSymbolAddress((void**)&bias_ptr, g_bias);
    cudaGetSymbolAddress((void**)&wqkvT_ptr, g_wqkvT);
    cudaGetSymbolAddress((void**)&woutT_ptr, g_woutT);

    const int SMEM_BYTES = 4 * TILEF * (int)sizeof(float);   // 73728
    static bool attr_set = false;
    if (!attr_set) {
        cudaFuncSetAttribute(mma_gemm,
            cudaFuncAttributeMaxDynamicSharedMemorySize, SMEM_BYTES);
        attr_set = true;
    }

    // 0) prep: bias table, weight transposes (+rna), x -> tf32
    bias_kernel<<<(NT * NT + 255) / 256, 256>>>(pos, bias_ptr);
    {
        dim3 blk(32, 32);
        transpose_kernel<<<dim3(QKV_N / 32, DIM / 32), blk>>>(w_qkv, wqkvT_ptr, DIM, QKV_N);
        transpose_kernel<<<dim3(DIM / 32, DIM / 32), blk>>>(w_out, woutT_ptr, DIM, DIM);
    }
    {
        int n4 = M_TOK * DIM / 4;
        tf32_round_kernel<<<(n4 + 255) / 256, 256>>>(x, xtf_ptr, n4);
    }

    // 1) qkv = x @ w_qkv   (tf32 mma.sync + cp.async)
    {
        dim3 grid(QKV_N / 128, M_TOK / 128);
        mma_gemm<<<grid, 256, SMEM_BYTES>>>(xtf_ptr, wqkvT_ptr, qkv_ptr, nullptr, QKV_N, DIM);
    }
    // 2) window attention
    {
        dim3 grid(64, HEADS, 32);
        attn_kernel<<<grid, 128>>>(qkv_ptr, bias_ptr, attn_ptr);
    }
    // 3) out = attn @ w_out + b_out
    {
        dim3 grid(DIM / 128, M_TOK / 128);
        mma_gemm<<<grid, 256, SMEM_BYTES>>>(attn_ptr, woutT_ptr, out, b_out, DIM, DIM);
    }
}

// round 7
// speedup vs baseline: 3.5564x; 1.1383x over previous
#include <cuda_runtime.h>
#include <cstdint>

#define M_TOK   100352      // 32 * 56 * 56
#define DIM     256
#define QKV_N   768
#define HEADS   8
#define HD      32
#define WS      7
#define NT      49
#define SCALE   0.17677669529663687f

#define NP 52
#define QS 36
#define KS 56
#define SS 53

// Scratch (device globals: allocation-free per harness rules)
__device__ float g_qkv[(size_t)M_TOK * QKV_N];   // 308 MB
__device__ float g_attn[(size_t)M_TOK * DIM];    // 103 MB (tf32-rounded at source)
__device__ float g_xtf[(size_t)M_TOK * DIM];     // 103 MB x pre-rounded to tf32
__device__ float g_bias[NT * NT];
__device__ float g_wqkvT[QKV_N * DIM];           // transposed + tf32-rounded
__device__ float g_woutT[DIM * DIM];             // transposed + tf32-rounded

__device__ __forceinline__ uint32_t f2tf32(float f) {
    uint32_t r;
    asm("cvt.rna.tf32.f32 %0, %1;" : "=r"(r) : "f"(f));
    return r;
}
__device__ __forceinline__ uint32_t smem_u32(const void* p) {
    uint32_t a;
    asm("{ .reg .u64 t; cvta.to.shared.u64 t, %1; cvt.u32.u64 %0, t; }"
        : "=r"(a) : "l"(p));
    return a;
}
__device__ __forceinline__ void cpasync16(uint32_t dst, const void* src) {
    asm volatile("cp.async.ca.shared.global [%0], [%1], 16;"
                 :: "r"(dst), "l"(src));
}

// ---------------------------------------------------------------------------
// tf32 mma.sync GEMM with cp.async 2-stage pipeline. (unchanged from R6)
// ---------------------------------------------------------------------------
#define TSTR 36
#define TILEF (128 * TSTR)
#define TILEB (TILEF * 4)

__global__ __launch_bounds__(256, 2) void mma_gemm(
    const float* __restrict__ A, const float* __restrict__ BT,
    float* __restrict__ C, const float* __restrict__ bias,
    int N, int K)
{
    extern __shared__ float sm[];
    const uint32_t smbase = smem_u32(sm);

    const int tid  = threadIdx.x;
    const int wid  = tid >> 5;
    const int lane = tid & 31;
    const int group = lane >> 2;
    const int tig   = lane & 3;
    const int m0w = (wid & 1) * 64;
    const int n0w = (wid >> 1) * 32;
    const int bm = blockIdx.y * 128;
    const int bn = blockIdx.x * 128;

    const int lrow = tid >> 3;
    const int lcf4 = tid & 7;

    float c[4][4][4];
#pragma unroll
    for (int mt = 0; mt < 4; mt++)
#pragma unroll
        for (int nt = 0; nt < 4; nt++)
#pragma unroll
            for (int r = 0; r < 4; r++) c[mt][nt][r] = 0.f;

    const int nch = K >> 5;
    const uint32_t doff0 = (uint32_t)(lrow * TSTR + lcf4 * 4) * 4;

    auto issue = [&](int cc, int b) {
        const int k0 = cc * 32;
        const uint32_t aBase = smbase + (uint32_t)b * 2 * TILEB + doff0;
        const uint32_t bBase = aBase + TILEB;
#pragma unroll
        for (int i = 0; i < 4; i++) {
            const int row = lrow + 32 * i;
            cpasync16(aBase + (uint32_t)i * 32 * TSTR * 4,
                      &A[(size_t)(bm + row) * K + k0 + lcf4 * 4]);
            cpasync16(bBase + (uint32_t)i * 32 * TSTR * 4,
                      &BT[(size_t)(bn + row) * K + k0 + lcf4 * 4]);
        }
    };

    issue(0, 0);
    asm volatile("cp.async.commit_group;");
    if (nch > 1) issue(1, 1);
    asm volatile("cp.async.commit_group;");

    for (int cidx = 0; cidx < nch; cidx++) {
        const int buf = cidx & 1;
        asm volatile("cp.async.wait_group 1;");
        __syncthreads();

        const uint32_t* As = (const uint32_t*)(sm + buf * 2 * TILEF);
        const uint32_t* Bs = (const uint32_t*)(sm + buf * 2 * TILEF + TILEF);
#pragma unroll
        for (int k8 = 0; k8 < 4; k8++) {
            const int kc = k8 * 8 + tig;
            uint32_t a[4][4], b[4][2];
#pragma unroll
            for (int mt = 0; mt < 4; mt++) {
                const int r0 = m0w + mt * 16 + group;
                a[mt][0] = As[r0 * TSTR + kc];
                a[mt][1] = As[(r0 + 8) * TSTR + kc];
                a[mt][2] = As[r0 * TSTR + kc + 4];
                a[mt][3] = As[(r0 + 8) * TSTR + kc + 4];
            }
#pragma unroll
            for (int nt = 0; nt < 4; nt++) {
                const int r0 = n0w + nt * 8 + group;
                b[nt][0] = Bs[r0 * TSTR + kc];
                b[nt][1] = Bs[r0 * TSTR + kc + 4];
            }
#pragma unroll
            for (int mt = 0; mt < 4; mt++)
#pragma unroll
                for (int nt = 0; nt < 4; nt++) {
                    asm volatile(
                        "mma.sync.aligned.m16n8k8.row.col.f32.tf32.tf32.f32 "
                        "{%0,%1,%2,%3}, {%4,%5,%6,%7}, {%8,%9}, {%0,%1,%2,%3};"
                        : "+f"(c[mt][nt][0]), "+f"(c[mt][nt][1]),
                          "+f"(c[mt][nt][2]), "+f"(c[mt][nt][3])
                        : "r"(a[mt][0]), "r"(a[mt][1]), "r"(a[mt][2]), "r"(a[mt][3]),
                          "r"(b[nt][0]), "r"(b[nt][1]));
                }
        }
        __syncthreads();
        if (cidx + 2 < nch) issue(cidx + 2, buf);
        asm volatile("cp.async.commit_group;");
    }

#pragma unroll
    for (int nt = 0; nt < 4; nt++) {
        const int col = bn + n0w + nt * 8 + tig * 2;
        float bv0 = 0.f, bv1 = 0.f;
        if (bias) { bv0 = bias[col]; bv1 = bias[col + 1]; }
#pragma unroll
        for (int mt = 0; mt < 4; mt++) {
            const int row = bm + m0w + mt * 16 + group;
            float2 v0 = make_float2(c[mt][nt][0] + bv0, c[mt][nt][1] + bv1);
            float2 v1 = make_float2(c[mt][nt][2] + bv0, c[mt][nt][3] + bv1);
            *(float2*)&C[(size_t)row * N + col]       = v0;
            *(float2*)&C[(size_t)(row + 8) * N + col] = v1;
        }
    }
}

// ---------------------------------------------------------------------------
__global__ void tf32_round_kernel(const float* __restrict__ in,
                                  float* __restrict__ out, int n4)
{
    int i = blockIdx.x * 256 + threadIdx.x;
    if (i < n4) {
        float4 v = ((const float4*)in)[i];
        v.x = __uint_as_float(f2tf32(v.x));
        v.y = __uint_as_float(f2tf32(v.y));
        v.z = __uint_as_float(f2tf32(v.z));
        v.w = __uint_as_float(f2tf32(v.w));
        ((float4*)out)[i] = v;
    }
}

__global__ void transpose_kernel(const float* __restrict__ W,
                                 float* __restrict__ WT, int R, int Cc)
{
    __shared__ float t[32][33];
    int x = blockIdx.x * 32 + threadIdx.x;
    int y = blockIdx.y * 32 + threadIdx.y;
    if (x < Cc && y < R) t[threadIdx.y][threadIdx.x] = W[y * Cc + x];
    __syncthreads();
    x = blockIdx.y * 32 + threadIdx.x;
    y = blockIdx.x * 32 + threadIdx.y;
    if (x < R && y < Cc)
        WT[y * R + x] = __uint_as_float(f2tf32(t[threadIdx.x][threadIdx.y]));
}

__global__ void bias_kernel(const float* __restrict__ pos_emb,
                            float* __restrict__ biasG)
{
    int e = blockIdx.x * 256 + threadIdx.x;
    if (e < NT * NT) {
        int i = e / NT, j = e - i * NT;
        int dx = j / WS - i / WS + (WS - 1);
        int dy = j % WS - i % WS + (WS - 1);
        biasG[e] = pos_emb[dx * (2 * WS - 1) + dy];
    }
}

// ---------------------------------------------------------------------------
// Window attention v3: conflict-free tile mapping, 2-thread/row softmax,
// no bias smem (L2-resident table via __ldg). 33KB smem -> 6 blocks/SM.
// ---------------------------------------------------------------------------
__global__ __launch_bounds__(128) void attn_kernel(
    const float* __restrict__ qkv,
    const float* __restrict__ biasG,
    float* __restrict__ out)
{
    __shared__ float q[NP][QS];
    __shared__ float kT[HD][KS];
    __shared__ float v[NT][QS];
    __shared__ float S[NP][SS];
    __shared__ int   rowbase[NT];

    const int tid = threadIdx.x;
    const int w = blockIdx.x;
    const int h = blockIdx.y;
    const int b = blockIdx.z;
    const int wr = w >> 3, wc = w & 7;

    if (tid < NT) {
        int ty = tid / WS, tx = tid - ty * WS;
        rowbase[tid] = (b * 56 + wr * WS + ty) * 56 + wc * WS + tx;
    }
    __syncthreads();

    // Gather q/k/v (k transposed into kT)
    for (int f = tid; f < NT * 8; f += 128) {
        int t = f >> 3, d4 = (f & 7) * 4;
        size_t base = (size_t)rowbase[t] * QKV_N + h * HD + d4;
        float4 qq = *(const float4*)&qkv[base];
        float4 kk = *(const float4*)&qkv[base + 256];
        float4 vv = *(const float4*)&qkv[base + 512];
        *(float4*)&q[t][d4] = qq;
        kT[d4 + 0][t] = kk.x;
        kT[d4 + 1][t] = kk.y;
        kT[d4 + 2][t] = kk.z;
        kT[d4 + 3][t] = kk.w;
        *(float4*)&v[t][d4] = vv;
    }
    __syncthreads();

    // Scores. Mapping it = T/13: q-loads broadcast within 13-lane groups,
    // kT-loads bank-spread (<=2-way). (R6 had it = T%13 -> ~13-way conflicts.)
    for (int T = tid; T < 169; T += 128) {
        int it = T / 13, jt = T - it * 13;
        int i0 = it * 4, j0 = jt * 4;
        float acc[4][4] = {};
#pragma unroll
        for (int d4 = 0; d4 < HD; d4 += 4) {
            float4 a[4], kk[4];
#pragma unroll
            for (int r = 0; r < 4; r++) a[r] = *(const float4*)&q[i0 + r][d4];
#pragma unroll
            for (int c = 0; c < 4; c++) kk[c] = *(const float4*)&kT[d4 + c][j0];
#pragma unroll
            for (int r = 0; r < 4; r++) {
                acc[r][0] += a[r].x * kk[0].x + a[r].y * kk[1].x + a[r].z * kk[2].x + a[r].w * kk[3].x;
                acc[r][1] += a[r].x * kk[0].y + a[r].y * kk[1].y + a[r].z * kk[2].y + a[r].w * kk[3].y;
                acc[r][2] += a[r].x * kk[0].z + a[r].y * kk[1].z + a[r].z * kk[2].z + a[r].w * kk[3].z;
                acc[r][3] += a[r].x * kk[0].w + a[r].y * kk[1].w + a[r].z * kk[2].w + a[r].w * kk[3].w;
            }
        }
#pragma unroll
        for (int r = 0; r < 4; r++)
#pragma unroll
            for (int c = 0; c < 4; c++)
                S[i0 + r][j0 + c] = acc[r][c];
    }
    __syncthreads();

    // Softmax: 2 threads per row (tid < 98), bias straight from L2.
    if (tid < 98) {
        const unsigned mask = (tid < 96) ? 0xffffffffu : 0x3u;
        const int row = tid >> 1;
        const int half = tid & 1;
        const int j0 = half ? 25 : 0;
        const int jn = half ? NT : 25;
        float* srow = S[row];
        const float* brow = &biasG[row * NT];
        float m = -1e30f;
        for (int j = j0; j < jn; j++) {
            float t = srow[j] * SCALE + __ldg(&brow[j]);
            srow[j] = t;
            m = fmaxf(m, t);
        }
        m = fmaxf(m, __shfl_xor_sync(mask, m, 1));
        float s = 0.f;
        for (int j = j0; j < jn; j++) {
            float e = __expf(srow[j] - m);
            srow[j] = e;
            s += e;
        }
        s += __shfl_xor_sync(mask, s, 1);
        float inv = 1.f / s;
        for (int j = j0; j < jn; j++) srow[j] *= inv;
    }
    __syncthreads();

    // PV (mapping unchanged: v-loads conflict-free, S scalar spread)
    for (int T = tid; T < 104; T += 128) {
        int it = T % 13, dt = T / 13;
        int i0 = it * 4, d0 = dt * 4;
        float4 acc0 = {0,0,0,0}, acc1 = {0,0,0,0}, acc2 = {0,0,0,0}, acc3 = {0,0,0,0};
        for (int j = 0; j < NT; j++) {
            float4 vv = *(const float4*)&v[j][d0];
            float s0 = S[i0 + 0][j], s1 = S[i0 + 1][j];
            float s2 = S[i0 + 2][j], s3 = S[i0 + 3][j];
            acc0.x += s0 * vv.x; acc0.y += s0 * vv.y; acc0.z += s0 * vv.z; acc0.w += s0 * vv.w;
            acc1.x += s1 * vv.x; acc1.y += s1 * vv.y; acc1.z += s1 * vv.z; acc1.w += s1 * vv.w;
            acc2.x += s2 * vv.x; acc2.y += s2 * vv.y; acc2.z += s2 * vv.z; acc2.w += s2 * vv.w;
            acc3.x += s3 * vv.x; acc3.y += s3 * vv.y; acc3.z += s3 * vv.z; acc3.w += s3 * vv.w;
        }
        float4 accs[4] = {acc0, acc1, acc2, acc3};
#pragma unroll
        for (int r = 0; r < 4; r++) {
            if (i0 + r < NT) {
                float4 o = accs[r];
                o.x = __uint_as_float(f2tf32(o.x));
                o.y = __uint_as_float(f2tf32(o.y));
                o.z = __uint_as_float(f2tf32(o.z));
                o.w = __uint_as_float(f2tf32(o.w));
                *(float4*)&out[(size_t)rowbase[i0 + r] * DIM + h * HD + d0] = o;
            }
        }
    }
}

// ---------------------------------------------------------------------------
extern "C" void kernel_launch(void* const* d_in, const int* in_sizes, int n_in,
                              void* d_out, int out_size)
{
    const float* x      = (const float*)d_in[0];
    const float* w_qkv  = (const float*)d_in[1];
    const float* w_out  = (const float*)d_in[2];
    const float* b_out  = (const float*)d_in[3];
    const float* pos    = (const float*)d_in[4];
    float* out = (float*)d_out;

    float *qkv_ptr, *attn_ptr, *xtf_ptr, *bias_ptr, *wqkvT_ptr, *woutT_ptr;
    cudaGetSymbolAddress((void**)&qkv_ptr,  g_qkv);
    cudaGetSymbolAddress((void**)&attn_ptr, g_attn);
    cudaGetSymbolAddress((void**)&xtf_ptr,  g_xtf);
    cudaGetSymbolAddress((void**)&bias_ptr, g_bias);
    cudaGetSymbolAddress((void**)&wqkvT_ptr, g_wqkvT);
    cudaGetSymbolAddress((void**)&woutT_ptr, g_woutT);

    const int SMEM_BYTES = 4 * TILEF * (int)sizeof(float);   // 73728
    static bool attr_set = false;
    if (!attr_set) {
        cudaFuncSetAttribute(mma_gemm,
            cudaFuncAttributeMaxDynamicSharedMemorySize, SMEM_BYTES);
        attr_set = true;
    }

    // 0) prep
    bias_kernel<<<(NT * NT + 255) / 256, 256>>>(pos, bias_ptr);
    {
        dim3 blk(32, 32);
        transpose_kernel<<<dim3(QKV_N / 32, DIM / 32), blk>>>(w_qkv, wqkvT_ptr, DIM, QKV_N);
        transpose_kernel<<<dim3(DIM / 32, DIM / 32), blk>>>(w_out, woutT_ptr, DIM, DIM);
    }
    {
        int n4 = M_TOK * DIM / 4;
        tf32_round_kernel<<<(n4 + 255) / 256, 256>>>(x, xtf_ptr, n4);
    }

    // 1) qkv = x @ w_qkv
    {
        dim3 grid(QKV_N / 128, M_TOK / 128);
        mma_gemm<<<grid, 256, SMEM_BYTES>>>(xtf_ptr, wqkvT_ptr, qkv_ptr, nullptr, QKV_N, DIM);
    }
    // 2) window attention
    {
        dim3 grid(64, HEADS, 32);
        attn_kernel<<<grid, 128>>>(qkv_ptr, bias_ptr, attn_ptr);
    }
    // 3) out = attn @ w_out + b_out
    {
        dim3 grid(DIM / 128, M_TOK / 128);
        mma_gemm<<<grid, 256, SMEM_BYTES>>>(attn_ptr, woutT_ptr, out, b_out, DIM, DIM);
    }
}

// round 8
// speedup vs baseline: 5.0016x; 1.4064x over previous
#include <cuda_runtime.h>
#include <cstdint>

#define M_TOK   100352      // 32 * 56 * 56
#define DIM     256
#define QKV_N   768
#define HEADS   8
#define HD      32
#define WS      7
#define NT      49
#define SCALE   0.17677669529663687f

// Scratch (device globals: allocation-free per harness rules)
__device__ float g_qkv[(size_t)M_TOK * QKV_N];   // 308 MB
__device__ float g_attn[(size_t)M_TOK * DIM];    // 103 MB (tf32-rounded at source)
__device__ float g_xtf[(size_t)M_TOK * DIM];     // 103 MB x pre-rounded to tf32
__device__ float g_bias[NT * NT];
__device__ float g_wqkvT[QKV_N * DIM];           // transposed + tf32-rounded
__device__ float g_woutT[DIM * DIM];             // transposed + tf32-rounded

__device__ __forceinline__ uint32_t f2tf32(float f) {
    uint32_t r;
    asm("cvt.rna.tf32.f32 %0, %1;" : "=r"(r) : "f"(f));
    return r;
}
__device__ __forceinline__ uint32_t smem_u32(const void* p) {
    uint32_t a;
    asm("{ .reg .u64 t; cvta.to.shared.u64 t, %1; cvt.u32.u64 %0, t; }"
        : "=r"(a) : "l"(p));
    return a;
}
__device__ __forceinline__ void cpasync16(uint32_t dst, const void* src) {
    asm volatile("cp.async.ca.shared.global [%0], [%1], 16;"
                 :: "r"(dst), "l"(src));
}
__device__ __forceinline__ void mma_tf32(float* c, uint32_t a0, uint32_t a1,
                                         uint32_t a2, uint32_t a3,
                                         uint32_t b0, uint32_t b1) {
    asm volatile(
        "mma.sync.aligned.m16n8k8.row.col.f32.tf32.tf32.f32 "
        "{%0,%1,%2,%3}, {%4,%5,%6,%7}, {%8,%9}, {%0,%1,%2,%3};"
        : "+f"(c[0]), "+f"(c[1]), "+f"(c[2]), "+f"(c[3])
        : "r"(a0), "r"(a1), "r"(a2), "r"(a3), "r"(b0), "r"(b1));
}

// ---------------------------------------------------------------------------
// tf32 mma.sync GEMM with cp.async 2-stage pipeline. (unchanged from R7)
// ---------------------------------------------------------------------------
#define TSTR 36
#define TILEF (128 * TSTR)
#define TILEB (TILEF * 4)

__global__ __launch_bounds__(256, 2) void mma_gemm(
    const float* __restrict__ A, const float* __restrict__ BT,
    float* __restrict__ C, const float* __restrict__ bias,
    int N, int K)
{
    extern __shared__ float sm[];
    const uint32_t smbase = smem_u32(sm);

    const int tid  = threadIdx.x;
    const int wid  = tid >> 5;
    const int lane = tid & 31;
    const int group = lane >> 2;
    const int tig   = lane & 3;
    const int m0w = (wid & 1) * 64;
    const int n0w = (wid >> 1) * 32;
    const int bm = blockIdx.y * 128;
    const int bn = blockIdx.x * 128;

    const int lrow = tid >> 3;
    const int lcf4 = tid & 7;

    float c[4][4][4];
#pragma unroll
    for (int mt = 0; mt < 4; mt++)
#pragma unroll
        for (int nt = 0; nt < 4; nt++)
#pragma unroll
            for (int r = 0; r < 4; r++) c[mt][nt][r] = 0.f;

    const int nch = K >> 5;
    const uint32_t doff0 = (uint32_t)(lrow * TSTR + lcf4 * 4) * 4;

    auto issue = [&](int cc, int b) {
        const int k0 = cc * 32;
        const uint32_t aBase = smbase + (uint32_t)b * 2 * TILEB + doff0;
        const uint32_t bBase = aBase + TILEB;
#pragma unroll
        for (int i = 0; i < 4; i++) {
            const int row = lrow + 32 * i;
            cpasync16(aBase + (uint32_t)i * 32 * TSTR * 4,
                      &A[(size_t)(bm + row) * K + k0 + lcf4 * 4]);
            cpasync16(bBase + (uint32_t)i * 32 * TSTR * 4,
                      &BT[(size_t)(bn + row) * K + k0 + lcf4 * 4]);
        }
    };

    issue(0, 0);
    asm volatile("cp.async.commit_group;");
    if (nch > 1) issue(1, 1);
    asm volatile("cp.async.commit_group;");

    for (int cidx = 0; cidx < nch; cidx++) {
        const int buf = cidx & 1;
        asm volatile("cp.async.wait_group 1;");
        __syncthreads();

        const uint32_t* As = (const uint32_t*)(sm + buf * 2 * TILEF);
        const uint32_t* Bs = (const uint32_t*)(sm + buf * 2 * TILEF + TILEF);
#pragma unroll
        for (int k8 = 0; k8 < 4; k8++) {
            const int kc = k8 * 8 + tig;
            uint32_t a[4][4], b[4][2];
#pragma unroll
            for (int mt = 0; mt < 4; mt++) {
                const int r0 = m0w + mt * 16 + group;
                a[mt][0] = As[r0 * TSTR + kc];
                a[mt][1] = As[(r0 + 8) * TSTR + kc];
                a[mt][2] = As[r0 * TSTR + kc + 4];
                a[mt][3] = As[(r0 + 8) * TSTR + kc + 4];
            }
#pragma unroll
            for (int nt = 0; nt < 4; nt++) {
                const int r0 = n0w + nt * 8 + group;
                b[nt][0] = Bs[r0 * TSTR + kc];
                b[nt][1] = Bs[r0 * TSTR + kc + 4];
            }
#pragma unroll
            for (int mt = 0; mt < 4; mt++)
#pragma unroll
                for (int nt = 0; nt < 4; nt++)
                    mma_tf32(c[mt][nt], a[mt][0], a[mt][1], a[mt][2], a[mt][3],
                             b[nt][0], b[nt][1]);
        }
        __syncthreads();
        if (cidx + 2 < nch) issue(cidx + 2, buf);
        asm volatile("cp.async.commit_group;");
    }

#pragma unroll
    for (int nt = 0; nt < 4; nt++) {
        const int col = bn + n0w + nt * 8 + tig * 2;
        float bv0 = 0.f, bv1 = 0.f;
        if (bias) { bv0 = bias[col]; bv1 = bias[col + 1]; }
#pragma unroll
        for (int mt = 0; mt < 4; mt++) {
            const int row = bm + m0w + mt * 16 + group;
            float2 v0 = make_float2(c[mt][nt][0] + bv0, c[mt][nt][1] + bv1);
            float2 v1 = make_float2(c[mt][nt][2] + bv0, c[mt][nt][3] + bv1);
            *(float2*)&C[(size_t)row * N + col]       = v0;
            *(float2*)&C[(size_t)(row + 8) * N + col] = v1;
        }
    }
}

// ---------------------------------------------------------------------------
__global__ void tf32_round_kernel(const float* __restrict__ in,
                                  float* __restrict__ out, int n4)
{
    int i = blockIdx.x * 256 + threadIdx.x;
    if (i < n4) {
        float4 v = ((const float4*)in)[i];
        v.x = __uint_as_float(f2tf32(v.x));
        v.y = __uint_as_float(f2tf32(v.y));
        v.z = __uint_as_float(f2tf32(v.z));
        v.w = __uint_as_float(f2tf32(v.w));
        ((float4*)out)[i] = v;
    }
}

__global__ void transpose_kernel(const float* __restrict__ W,
                                 float* __restrict__ WT, int R, int Cc)
{
    __shared__ float t[32][33];
    int x = blockIdx.x * 32 + threadIdx.x;
    int y = blockIdx.y * 32 + threadIdx.y;
    if (x < Cc && y < R) t[threadIdx.y][threadIdx.x] = W[y * Cc + x];
    __syncthreads();
    x = blockIdx.y * 32 + threadIdx.x;
    y = blockIdx.x * 32 + threadIdx.y;
    if (x < R && y < Cc)
        WT[y * R + x] = __uint_as_float(f2tf32(t[threadIdx.x][threadIdx.y]));
}

__global__ void bias_kernel(const float* __restrict__ pos_emb,
                            float* __restrict__ biasG)
{
    int e = blockIdx.x * 256 + threadIdx.x;
    if (e < NT * NT) {
        int i = e / NT, j = e - i * NT;
        int dx = j / WS - i / WS + (WS - 1);
        int dy = j % WS - i % WS + (WS - 1);
        biasG[e] = pos_emb[dx * (2 * WS - 1) + dy];
    }
}

// ---------------------------------------------------------------------------
// Window attention v4: flash-style, mma.sync tf32, S/P register-resident.
// Block = (window, head, batch), 4 warps; warp wm owns Q rows [16wm,16wm+16).
// QK: 28 m16n8k8 per warp; softmax on C-fragments w/ shfl; PV: 28 mma with
// P->A fragment conversion via shfl; divide-by-sum at the store.
// ---------------------------------------------------------------------------
#define AST 36   // smem row stride (floats) for q/k/v

__global__ __launch_bounds__(128) void attn_kernel(
    const float* __restrict__ qkv,
    const float* __restrict__ biasG,
    float* __restrict__ out)
{
    __shared__ float qs[64 * AST];   // rows 49..63 zero (cols 0..31)
    __shared__ float ks[56 * AST];   // rows 49..55 zero
    __shared__ float vs[56 * AST];
    __shared__ int   rowbase[NT];

    const int tid = threadIdx.x;
    const int wm  = tid >> 5;
    const int lane = tid & 31;
    const int group = lane >> 2;     // 0..7
    const int tig   = lane & 3;      // 0..3
    const int w = blockIdx.x;
    const int h = blockIdx.y;
    const int b = blockIdx.z;
    const int wr = w >> 3, wc = w & 7;

    if (tid < NT) {
        int ty = tid / WS, tx = tid - ty * WS;
        rowbase[tid] = (b * 56 + wr * WS + ty) * 56 + wc * WS + tx;
    }
    // zero pad rows (cols 0..31 suffice: fragments never read cols >= 32)
    for (int i = tid; i < 15 * 32; i += 128) {
        int r = 49 + i / 32, cidx = i & 31;
        qs[r * AST + cidx] = 0.f;
    }
    for (int i = tid; i < 7 * 32; i += 128) {
        int r = 49 + i / 32, cidx = i & 31;
        ks[r * AST + cidx] = 0.f;
        vs[r * AST + cidx] = 0.f;
    }
    __syncthreads();

    // Gather q/k/v rows (tf32-rounded at store)
    for (int f = tid; f < NT * 8; f += 128) {
        int t = f >> 3, d4 = (f & 7) * 4;
        size_t base = (size_t)rowbase[t] * QKV_N + h * HD + d4;
        float4 qq = *(const float4*)&qkv[base];
        float4 kk = *(const float4*)&qkv[base + 256];
        float4 vv = *(const float4*)&qkv[base + 512];
        float* qp = &qs[t * AST + d4];
        float* kp = &ks[t * AST + d4];
        float* vp = &vs[t * AST + d4];
        qp[0] = __uint_as_float(f2tf32(qq.x)); qp[1] = __uint_as_float(f2tf32(qq.y));
        qp[2] = __uint_as_float(f2tf32(qq.z)); qp[3] = __uint_as_float(f2tf32(qq.w));
        kp[0] = __uint_as_float(f2tf32(kk.x)); kp[1] = __uint_as_float(f2tf32(kk.y));
        kp[2] = __uint_as_float(f2tf32(kk.z)); kp[3] = __uint_as_float(f2tf32(kk.w));
        vp[0] = __uint_as_float(f2tf32(vv.x)); vp[1] = __uint_as_float(f2tf32(vv.y));
        vp[2] = __uint_as_float(f2tf32(vv.z)); vp[3] = __uint_as_float(f2tf32(vv.w));
    }
    __syncthreads();

    const uint32_t* qb = (const uint32_t*)qs;
    const uint32_t* kb = (const uint32_t*)ks;
    const uint32_t* vb = (const uint32_t*)vs;
    const int row_lo = 16 * wm + group;
    const int row_hi = row_lo + 8;

    // ---- QK^T: S fragments sfrag[jt][0..3] ----
    float sfrag[7][4];
#pragma unroll
    for (int jt = 0; jt < 7; jt++)
#pragma unroll
        for (int r = 0; r < 4; r++) sfrag[jt][r] = 0.f;

#pragma unroll
    for (int kk = 0; kk < 4; kk++) {
        const int kc = 8 * kk + tig;
        uint32_t a0 = qb[row_lo * AST + kc];
        uint32_t a1 = qb[row_hi * AST + kc];
        uint32_t a2 = qb[row_lo * AST + kc + 4];
        uint32_t a3 = qb[row_hi * AST + kc + 4];
#pragma unroll
        for (int jt = 0; jt < 7; jt++) {
            const int j = 8 * jt + group;
            uint32_t b0 = kb[j * AST + kc];
            uint32_t b1 = kb[j * AST + kc + 4];
            mma_tf32(sfrag[jt], a0, a1, a2, a3, b0, b1);
        }
    }

    // ---- softmax on fragments ----
    // c0: (row_lo, 8jt+2tig)  c1: (row_lo, 8jt+2tig+1)
    // c2: (row_hi, 8jt+2tig)  c3: (row_hi, 8jt+2tig+1)
    float m_lo = -1e30f, m_hi = -1e30f;
#pragma unroll
    for (int jt = 0; jt < 7; jt++) {
        const int col0 = 8 * jt + 2 * tig;
#pragma unroll
        for (int r = 0; r < 4; r++) {
            const int col = col0 + (r & 1);
            const int row = (r < 2) ? row_lo : row_hi;
            float val;
            if (row < NT && col < NT)
                val = sfrag[jt][r] * SCALE + __ldg(&biasG[row * NT + col]);
            else
                val = -1e30f;
            sfrag[jt][r] = val;
            if (r < 2) m_lo = fmaxf(m_lo, val); else m_hi = fmaxf(m_hi, val);
        }
    }
    m_lo = fmaxf(m_lo, __shfl_xor_sync(0xffffffffu, m_lo, 1));
    m_lo = fmaxf(m_lo, __shfl_xor_sync(0xffffffffu, m_lo, 2));
    m_hi = fmaxf(m_hi, __shfl_xor_sync(0xffffffffu, m_hi, 1));
    m_hi = fmaxf(m_hi, __shfl_xor_sync(0xffffffffu, m_hi, 2));

    float s_lo = 0.f, s_hi = 0.f;
#pragma unroll
    for (int jt = 0; jt < 7; jt++) {
#pragma unroll
        for (int r = 0; r < 4; r++) {
            float e = __expf(sfrag[jt][r] - ((r < 2) ? m_lo : m_hi));
            sfrag[jt][r] = e;
            if (r < 2) s_lo += e; else s_hi += e;
        }
    }
    s_lo += __shfl_xor_sync(0xffffffffu, s_lo, 1);
    s_lo += __shfl_xor_sync(0xffffffffu, s_lo, 2);
    s_hi += __shfl_xor_sync(0xffffffffu, s_hi, 1);
    s_hi += __shfl_xor_sync(0xffffffffu, s_hi, 2);

    // ---- PV: O fragments o[nt][0..3] ----
    float o[4][4];
#pragma unroll
    for (int nt = 0; nt < 4; nt++)
#pragma unroll
        for (int r = 0; r < 4; r++) o[nt][r] = 0.f;

    const int srcA = (lane & ~3) | (tig >> 1);
    const int srcB = srcA + 2;
    const bool odd = (tig & 1);

#pragma unroll
    for (int kt = 0; kt < 7; kt++) {
        // P fragment conversion: C-layout cols {2t,2t+1} -> A-layout k {t,t+4}
        float x0 = sfrag[kt][0], x1 = sfrag[kt][1];
        float x2 = sfrag[kt][2], x3 = sfrag[kt][3];
        float y0  = __shfl_sync(0xffffffffu, x0, srcA);
        float y1  = __shfl_sync(0xffffffffu, x1, srcA);
        float y0b = __shfl_sync(0xffffffffu, x0, srcB);
        float y1b = __shfl_sync(0xffffffffu, x1, srcB);
        float z0  = __shfl_sync(0xffffffffu, x2, srcA);
        float z1  = __shfl_sync(0xffffffffu, x3, srcA);
        float z0b = __shfl_sync(0xffffffffu, x2, srcB);
        float z1b = __shfl_sync(0xffffffffu, x3, srcB);
        uint32_t a0 = f2tf32(odd ? y1  : y0);    // P[row_lo][8kt+tig]
        uint32_t a1 = f2tf32(odd ? z1  : z0);    // P[row_hi][8kt+tig]
        uint32_t a2 = f2tf32(odd ? y1b : y0b);   // P[row_lo][8kt+tig+4]
        uint32_t a3 = f2tf32(odd ? z1b : z0b);   // P[row_hi][8kt+tig+4]

        const int j0 = 8 * kt + tig;
#pragma unroll
        for (int nt = 0; nt < 4; nt++) {
            const int d0 = 8 * nt + group;
            uint32_t b0 = vb[j0 * AST + d0];
            uint32_t b1 = vb[(j0 + 4) * AST + d0];
            mma_tf32(o[nt], a0, a1, a2, a3, b0, b1);
        }
    }

    // ---- store (divide by row sum, tf32-round for GEMM2) ----
    const float inv_lo = 1.f / s_lo;
    const float inv_hi = 1.f / s_hi;
    if (row_lo < NT) {
        float* orow = &out[(size_t)rowbase[row_lo] * DIM + h * HD];
#pragma unroll
        for (int nt = 0; nt < 4; nt++) {
            float2 v;
            v.x = __uint_as_float(f2tf32(o[nt][0] * inv_lo));
            v.y = __uint_as_float(f2tf32(o[nt][1] * inv_lo));
            *(float2*)&orow[8 * nt + 2 * tig] = v;
        }
    }
    if (row_hi < NT) {
        float* orow = &out[(size_t)rowbase[row_hi] * DIM + h * HD];
#pragma unroll
        for (int nt = 0; nt < 4; nt++) {
            float2 v;
            v.x = __uint_as_float(f2tf32(o[nt][2] * inv_hi));
            v.y = __uint_as_float(f2tf32(o[nt][3] * inv_hi));
            *(float2*)&orow[8 * nt + 2 * tig] = v;
        }
    }
}

// ---------------------------------------------------------------------------
extern "C" void kernel_launch(void* const* d_in, const int* in_sizes, int n_in,
                              void* d_out, int out_size)
{
    const float* x      = (const float*)d_in[0];
    const float* w_qkv  = (const float*)d_in[1];
    const float* w_out  = (const float*)d_in[2];
    const float* b_out  = (const float*)d_in[3];
    const float* pos    = (const float*)d_in[4];
    float* out = (float*)d_out;

    float *qkv_ptr, *attn_ptr, *xtf_ptr, *bias_ptr, *wqkvT_ptr, *woutT_ptr;
    cudaGetSymbolAddress((void**)&qkv_ptr,  g_qkv);
    cudaGetSymbolAddress((void**)&attn_ptr, g_attn);
    cudaGetSymbolAddress((void**)&xtf_ptr,  g_xtf);
    cudaGetSymbolAddress((void**)&bias_ptr, g_bias);
    cudaGetSymbolAddress((void**)&wqkvT_ptr, g_wqkvT);
    cudaGetSymbolAddress((void**)&woutT_ptr, g_woutT);

    const int SMEM_BYTES = 4 * TILEF * (int)sizeof(float);   // 73728
    static bool attr_set = false;
    if (!attr_set) {
        cudaFuncSetAttribute(mma_gemm,
            cudaFuncAttributeMaxDynamicSharedMemorySize, SMEM_BYTES);
        attr_set = true;
    }

    // 0) prep
    bias_kernel<<<(NT * NT + 255) / 256, 256>>>(pos, bias_ptr);
    {
        dim3 blk(32, 32);
        transpose_kernel<<<dim3(QKV_N / 32, DIM / 32), blk>>>(w_qkv, wqkvT_ptr, DIM, QKV_N);
        transpose_kernel<<<dim3(DIM / 32, DIM / 32), blk>>>(w_out, woutT_ptr, DIM, DIM);
    }
    {
        int n4 = M_TOK * DIM / 4;
        tf32_round_kernel<<<(n4 + 255) / 256, 256>>>(x, xtf_ptr, n4);
    }

    // 1) qkv = x @ w_qkv
    {
        dim3 grid(QKV_N / 128, M_TOK / 128);
        mma_gemm<<<grid, 256, SMEM_BYTES>>>(xtf_ptr, wqkvT_ptr, qkv_ptr, nullptr, QKV_N, DIM);
    }
    // 2) window attention (flash-style mma)
    {
        dim3 grid(64, HEADS, 32);
        attn_kernel<<<grid, 128>>>(qkv_ptr, bias_ptr, attn_ptr);
    }
    // 3) out = attn @ w_out + b_out
    {
        dim3 grid(DIM / 128, M_TOK / 128);
        mma_gemm<<<grid, 256, SMEM_BYTES>>>(attn_ptr, woutT_ptr, out, b_out, DIM, DIM);
    }
}